// round 6
// baseline (speedup 1.0000x reference)
#include <cuda_runtime.h>
#include <cuda_fp16.h>
#include <cstdint>

// out[B=256, N] = (inputs @ features^T) / 0.07
// R5: fp16 mma.sync GEMM, A-resident-in-smem.
// CTA: 512 thr / 16 warps (4m x 4n, warp 64x32), tile M=256 x N=128.
// A (256x256 fp16, 132KB @ 528B stride) loaded ONCE via cp.async; only F is
// pipelined (KC=64, 4 iters, double-buffered 144B-stride stages). Halves the
// sync count of R3 and removes per-iter A staging. F read once per n-tile
// (full M per CTA — R4 showed splitting M doubles F traffic and regresses).

#define KC 64
#define NITER 4
#define NT 128
#define AROWB 528u             // 512B K-row + 16B pad: conflict-free ldmatrix
#define FROWB 144u             // 128B chunk-row + 16B pad
#define ASZ (256u * 528u)      // 135168
#define FSTAGE (128u * 144u)   // 18432
#define SMEM_TOTAL (ASZ + 2 * FSTAGE)   // 172032
#define SCALE (1.0f / 0.07f)

__device__ __align__(16) __half g_A16[256 * 256];

// ---------------- helpers ----------------
__device__ __forceinline__ uint32_t smem_u32(const void* p) {
    uint32_t r;
    asm("{ .reg .u64 t; cvta.to.shared.u64 t, %1; cvt.u32.u64 %0, t; }" : "=r"(r) : "l"(p));
    return r;
}
__device__ __forceinline__ uint32_t pack_f16x2(float hi, float lo) {
    uint32_t r;
    asm("cvt.rn.f16x2.f32 %0, %1, %2;" : "=r"(r) : "f"(hi), "f"(lo));
    return r;
}
__device__ __forceinline__ void sts128(uint32_t a, uint32_t x, uint32_t y, uint32_t z, uint32_t w) {
    asm volatile("st.shared.v4.b32 [%0], {%1,%2,%3,%4};"
                 :: "r"(a), "r"(x), "r"(y), "r"(z), "r"(w) : "memory");
}
__device__ __forceinline__ void ldm4(uint32_t* r, uint32_t a) {
    asm volatile("ldmatrix.sync.aligned.m8n8.x4.shared.b16 {%0,%1,%2,%3}, [%4];"
                 : "=r"(r[0]), "=r"(r[1]), "=r"(r[2]), "=r"(r[3]) : "r"(a));
}
__device__ __forceinline__ void mma16816(float* d, const uint32_t* a, const uint32_t* b) {
    asm volatile("mma.sync.aligned.m16n8k16.row.col.f32.f16.f16.f32 "
                 "{%0,%1,%2,%3}, {%4,%5,%6,%7}, {%8,%9}, {%0,%1,%2,%3};"
                 : "+f"(d[0]), "+f"(d[1]), "+f"(d[2]), "+f"(d[3])
                 : "r"(a[0]), "r"(a[1]), "r"(a[2]), "r"(a[3]), "r"(b[0]), "r"(b[1]));
}
__device__ __forceinline__ void cp_async16(uint32_t dst, const void* src) {
    asm volatile("cp.async.cg.shared.global [%0], [%1], 16;" :: "r"(dst), "l"(src) : "memory");
}
#define CP_COMMIT asm volatile("cp.async.commit_group;" ::: "memory")
#define CP_WAIT0  asm volatile("cp.async.wait_group 0;" ::: "memory")

// ---------------- A convert kernel ----------------
__global__ void sct_cvtA(const float* __restrict__ A) {
    int i = blockIdx.x * 256 + threadIdx.x;   // 65536 elems
    g_A16[i] = __float2half_rn(A[i]);
}

// ---------------- main GEMM ----------------
__global__ __launch_bounds__(512, 1)
void sct_mma_kernel(const float* __restrict__ F, float* __restrict__ C, int N)
{
    extern __shared__ char smem[];
    const uint32_t sb = smem_u32(smem);      // A resident at sb, F stages after
    const uint32_t fb = sb + ASZ;
    const int tid  = threadIdx.x;
    const int lane = tid & 31;
    const int wid  = tid >> 5;
    const int n0   = blockIdx.x * NT;

    // ---- A residency load: 256 rows x 512B = 8192 granules, 16/thread ----
    {
        const int row  = tid >> 1;           // 2 threads per row
        const int half = tid & 1;            // 256B halves
        const uint32_t dst = row * AROWB + half * 256u;
        const __half* src = g_A16 + row * 256 + half * 128;
        #pragma unroll
        for (int i = 0; i < 16; i++)
            cp_async16(sb + dst + i * 16u, src + i * 8);
        CP_COMMIT;
    }

    // ---- F staging: row = tid>>2 (0..127), quarter = tid&3 -> 16 floats ----
    const int frow = tid >> 2;
    const int fq   = tid & 3;
    const int fn   = n0 + frow;
    const bool fvalid = (fn < N);
    const float* fsrc = F + (size_t)fn * 256 + fq * 16;
    const uint32_t f_sts = (uint32_t)frow * FROWB + (uint32_t)fq * 32u;

    // ---- warp tiling: 4 m-warps x 4 n-warps, warp tile 64x32 ----
    const int wm = wid & 3;
    const int wn = wid >> 2;
    const int mbase = wm * 64;
    const int nb    = wn * 32;

    const uint32_t afrag = (uint32_t)(mbase + (lane & 15)) * AROWB + (uint32_t)((lane >> 4) * 16);
    const uint32_t bfrag = (uint32_t)(nb + (lane & 7) + ((lane >> 4) << 3)) * FROWB
                         + (uint32_t)(((lane >> 3) & 1) << 4);

    float acc[4][4][4];
    #pragma unroll
    for (int i = 0; i < 4; i++)
        #pragma unroll
        for (int j = 0; j < 4; j++)
            #pragma unroll
            for (int q = 0; q < 4; q++) acc[i][j][q] = 0.0f;

    float4 pf0, pf1, pf2, pf3;

    auto ldgF = [&](int c) {
        if (fvalid) {
            const float4* p = (const float4*)(fsrc + c * KC);
            pf0 = p[0]; pf1 = p[1]; pf2 = p[2]; pf3 = p[3];
        } else {
            pf0 = pf1 = pf2 = pf3 = make_float4(0.f, 0.f, 0.f, 0.f);
        }
    };
    auto stsF = [&](int s) {
        const uint32_t d = fb + s * FSTAGE + f_sts;
        sts128(d,      pack_f16x2(pf0.y, pf0.x), pack_f16x2(pf0.w, pf0.z),
                       pack_f16x2(pf1.y, pf1.x), pack_f16x2(pf1.w, pf1.z));
        sts128(d + 16, pack_f16x2(pf2.y, pf2.x), pack_f16x2(pf2.w, pf2.z),
                       pack_f16x2(pf3.y, pf3.x), pack_f16x2(pf3.w, pf3.z));
    };
    auto compute = [&](int s, int c) {
        const uint32_t fst = fb + s * FSTAGE;
        const uint32_t act = c * (KC * 2);            // byte offset into A K-dim
        #pragma unroll
        for (int ks = 0; ks < 4; ks++) {              // 4 k16 slices in KC=64
            const uint32_t ko = ks * 32;
            uint32_t b0[4], b1[4], a[4][4];
            ldm4(b0, fst + bfrag + ko);               // n-tiles 0,1
            ldm4(b1, fst + bfrag + 16 * FROWB + ko);  // n-tiles 2,3
            #pragma unroll
            for (int i = 0; i < 4; i++)
                ldm4(a[i], sb + afrag + (uint32_t)i * (16 * AROWB) + act + ko);
            #pragma unroll
            for (int i = 0; i < 4; i++) {
                mma16816(acc[i][0], a[i], b0 + 0);
                mma16816(acc[i][1], a[i], b0 + 2);
                mma16816(acc[i][2], a[i], b1 + 0);
                mma16816(acc[i][3], a[i], b1 + 2);
            }
        }
    };

    // ---- prologue: F chunk 0 + wait A ----
    ldgF(0);
    stsF(0);
    CP_WAIT0;          // A resident
    __syncthreads();

    // ---- mainloop: 4 chunks, F double-buffered ----
    for (int c = 0; c < NITER; c++) {
        const int cur = c & 1;
        if (c + 1 < NITER) ldgF(c + 1);
        compute(cur, c);
        if (c + 1 < NITER) {
            __syncthreads();          // stage (cur^1) free: last reader done
            stsF(cur ^ 1);
            __syncthreads();
        }
    }

    // ---- epilogue ----
    #pragma unroll
    for (int i = 0; i < 4; i++) {
        const int m = mbase + i * 16 + (lane >> 2);
        #pragma unroll
        for (int j = 0; j < 4; j++) {
            const int n = n0 + nb + j * 8 + (lane & 3) * 2;
            if (n < N) {   // N even, n even -> n+1 also valid
                float* p0 = C + (size_t)m * N + n;
                float* p1 = C + (size_t)(m + 8) * N + n;
                *(float2*)p0 = make_float2(acc[i][j][0] * SCALE, acc[i][j][1] * SCALE);
                *(float2*)p1 = make_float2(acc[i][j][2] * SCALE, acc[i][j][3] * SCALE);
            }
        }
    }
}

// ---------------- launch ----------------
extern "C" void kernel_launch(void* const* d_in, const int* in_sizes, int n_in,
                              void* d_out, int out_size)
{
    const float* inputs   = (const float*)d_in[0];  // [256, 256]
    const float* features = (const float*)d_in[2];  // [N, 256]
    const int D = 256;
    const int N = in_sizes[2] / D;

    sct_cvtA<<<256, 256>>>(inputs);

    cudaFuncSetAttribute(sct_mma_kernel, cudaFuncAttributeMaxDynamicSharedMemorySize, SMEM_TOTAL);
    int grid = (N + NT - 1) / NT;
    sct_mma_kernel<<<grid, 512, SMEM_TOTAL>>>(features, (float*)d_out, N);
}

// round 7
// speedup vs baseline: 1.2257x; 1.2257x over previous
#include <cuda_runtime.h>
#include <cuda_fp16.h>
#include <cstdint>

// out[B=256, N] = (inputs @ features^T) / 0.07
// R6: fp16 mma.sync GEMM tuned for occupancy 3 (24 warps/SM).
// CTA: 256 thr / 8 warps (4m x 2n), warp tile 32x32 (acc = 32 regs),
// tile M=128 x N=64, K=256 in 8x KC=32. A staged via cp.async (no regs),
// F prefetch only 8 regs -> total regs fits 3 CTAs/SM via launch_bounds(256,3).
// R3's single-sync double-buffer pipeline. m-halves of each n-tile are
// bid-adjacent so the pair's F reads hit L2.

#define KC 32
#define NITER 8
#define NT 64
#define MT 128
#define ROWB 80u               // 64B k-row + 16B pad: conflict-free ldmatrix
#define ASTAGE 10240u          // 128 * 80
#define FSTAGE 5120u           // 64 * 80
#define SMEM_TOTAL (2 * 10240 + 2 * 5120)   // 30720
#define SCALE (1.0f / 0.07f)

__device__ __align__(16) __half g_A16[256 * 256];

// ---------------- helpers ----------------
__device__ __forceinline__ uint32_t smem_u32(const void* p) {
    uint32_t r;
    asm("{ .reg .u64 t; cvta.to.shared.u64 t, %1; cvt.u32.u64 %0, t; }" : "=r"(r) : "l"(p));
    return r;
}
__device__ __forceinline__ uint32_t pack_f16x2(float hi, float lo) {
    uint32_t r;
    asm("cvt.rn.f16x2.f32 %0, %1, %2;" : "=r"(r) : "f"(hi), "f"(lo));
    return r;
}
__device__ __forceinline__ void sts128(uint32_t a, uint32_t x, uint32_t y, uint32_t z, uint32_t w) {
    asm volatile("st.shared.v4.b32 [%0], {%1,%2,%3,%4};"
                 :: "r"(a), "r"(x), "r"(y), "r"(z), "r"(w) : "memory");
}
__device__ __forceinline__ void ldm4(uint32_t* r, uint32_t a) {
    asm volatile("ldmatrix.sync.aligned.m8n8.x4.shared.b16 {%0,%1,%2,%3}, [%4];"
                 : "=r"(r[0]), "=r"(r[1]), "=r"(r[2]), "=r"(r[3]) : "r"(a));
}
__device__ __forceinline__ void mma16816(float* d, const uint32_t* a, const uint32_t* b) {
    asm volatile("mma.sync.aligned.m16n8k16.row.col.f32.f16.f16.f32 "
                 "{%0,%1,%2,%3}, {%4,%5,%6,%7}, {%8,%9}, {%0,%1,%2,%3};"
                 : "+f"(d[0]), "+f"(d[1]), "+f"(d[2]), "+f"(d[3])
                 : "r"(a[0]), "r"(a[1]), "r"(a[2]), "r"(a[3]), "r"(b[0]), "r"(b[1]));
}
__device__ __forceinline__ void cp_async16(uint32_t dst, const void* src) {
    asm volatile("cp.async.cg.shared.global [%0], [%1], 16;" :: "r"(dst), "l"(src) : "memory");
}
#define CP_COMMIT asm volatile("cp.async.commit_group;" ::: "memory")
#define CP_WAIT0  asm volatile("cp.async.wait_group 0;" ::: "memory")

// ---------------- A convert kernel ----------------
__global__ void sct_cvtA(const float* __restrict__ A) {
    int i = blockIdx.x * 256 + threadIdx.x;   // 65536 elems
    g_A16[i] = __float2half_rn(A[i]);
}

// ---------------- main GEMM ----------------
__global__ __launch_bounds__(256, 3)
void sct_mma_kernel(const float* __restrict__ F, float* __restrict__ C, int N)
{
    extern __shared__ char smem[];
    const uint32_t sb = smem_u32(smem);          // A stages
    const uint32_t fb = sb + 2 * ASTAGE;         // F stages
    const int tid  = threadIdx.x;
    const int lane = tid & 31;
    const int wid  = tid >> 5;
    const int m0   = blockIdx.x * MT;            // 0 or 128 (bid-adjacent pair)
    const int n0   = blockIdx.y * NT;

    // A staging: 128 rows x 64B = 512 granules, 2 per thread (same row)
    const int ar = tid >> 1;                     // 0..127
    const int aq = tid & 1;                      // 32B half of row
    const uint32_t a_dst = (uint32_t)ar * ROWB + (uint32_t)aq * 32u;
    const __half* a_src = g_A16 + (m0 + ar) * 256 + aq * 16;

    // F staging: row = tid>>2 (0..63), quarter = tid&3 -> 8 floats
    const int frow = tid >> 2;
    const int fq   = tid & 3;
    const int fn   = n0 + frow;
    const bool fvalid = (fn < N);
    const float* fsrc = F + (size_t)fn * 256 + fq * 8;
    const uint32_t f_sts = (uint32_t)frow * ROWB + (uint32_t)fq * 16u;

    // warp tiling: 4 m-warps x 2 n-warps, warp tile 32x32
    const int wm = wid & 3;
    const int wn = wid >> 2;
    const int mbase = wm * 32;
    const int nb    = wn * 32;

    const uint32_t afrag = (uint32_t)(mbase + (lane & 15)) * ROWB + (uint32_t)((lane >> 4) * 16);
    const uint32_t bfrag = (uint32_t)(nb + (lane & 7) + ((lane >> 4) << 3)) * ROWB
                         + (uint32_t)(((lane >> 3) & 1) << 4);

    float acc[2][4][4];
    #pragma unroll
    for (int i = 0; i < 2; i++)
        #pragma unroll
        for (int j = 0; j < 4; j++)
            #pragma unroll
            for (int q = 0; q < 4; q++) acc[i][j][q] = 0.0f;

    float4 pf0, pf1;

    auto cpA = [&](int s, int c) {
        const uint32_t dst = sb + s * ASTAGE + a_dst;
        const __half* src = a_src + c * KC;
        cp_async16(dst, src);
        cp_async16(dst + 16, src + 8);
    };
    auto ldgF = [&](int c) {
        if (fvalid) {
            const float4* p = (const float4*)(fsrc + c * KC);
            pf0 = p[0]; pf1 = p[1];
        } else {
            pf0 = pf1 = make_float4(0.f, 0.f, 0.f, 0.f);
        }
    };
    auto stsF = [&](int s) {
        sts128(fb + s * FSTAGE + f_sts,
               pack_f16x2(pf0.y, pf0.x), pack_f16x2(pf0.w, pf0.z),
               pack_f16x2(pf1.y, pf1.x), pack_f16x2(pf1.w, pf1.z));
    };
    auto compute = [&](int s) {
        const uint32_t ast = sb + s * ASTAGE;
        const uint32_t fst = fb + s * FSTAGE;
        #pragma unroll
        for (int ks = 0; ks < 2; ks++) {
            const uint32_t ko = ks * 32;
            uint32_t b0[4], b1[4], a[2][4];
            ldm4(b0, fst + bfrag + ko);                  // n-tiles 0,1
            ldm4(b1, fst + bfrag + 16 * ROWB + ko);      // n-tiles 2,3
            #pragma unroll
            for (int i = 0; i < 2; i++)
                ldm4(a[i], ast + afrag + (uint32_t)i * (16 * ROWB) + ko);
            #pragma unroll
            for (int i = 0; i < 2; i++) {
                mma16816(acc[i][0], a[i], b0 + 0);
                mma16816(acc[i][1], a[i], b0 + 2);
                mma16816(acc[i][2], a[i], b1 + 0);
                mma16816(acc[i][3], a[i], b1 + 2);
            }
        }
    };

    // ---- prologue ----
    cpA(0, 0); CP_COMMIT;
    ldgF(0);
    stsF(0);
    CP_WAIT0;
    __syncthreads();

    // ---- mainloop (single sync per iter) ----
    for (int c = 0; c < NITER; c++) {
        const int cur = c & 1;
        const int nxt = cur ^ 1;
        if (c + 1 < NITER) {
            cpA(nxt, c + 1); CP_COMMIT;
            ldgF(c + 1);
        }
        compute(cur);
        if (c + 1 < NITER) {
            stsF(nxt);
            CP_WAIT0;
            __syncthreads();
        }
    }

    // ---- epilogue ----
    #pragma unroll
    for (int i = 0; i < 2; i++) {
        const int m = m0 + mbase + i * 16 + (lane >> 2);
        #pragma unroll
        for (int j = 0; j < 4; j++) {
            const int n = n0 + nb + j * 8 + (lane & 3) * 2;
            if (n < N) {   // N even, n even -> n+1 also valid
                float* p0 = C + (size_t)m * N + n;
                float* p1 = C + (size_t)(m + 8) * N + n;
                *(float2*)p0 = make_float2(acc[i][j][0] * SCALE, acc[i][j][1] * SCALE);
                *(float2*)p1 = make_float2(acc[i][j][2] * SCALE, acc[i][j][3] * SCALE);
            }
        }
    }
}

// ---------------- launch ----------------
extern "C" void kernel_launch(void* const* d_in, const int* in_sizes, int n_in,
                              void* d_out, int out_size)
{
    const float* inputs   = (const float*)d_in[0];  // [256, 256]
    const float* features = (const float*)d_in[2];  // [N, 256]
    const int D = 256;
    const int N = in_sizes[2] / D;

    sct_cvtA<<<256, 256>>>(inputs);

    cudaFuncSetAttribute(sct_mma_kernel, cudaFuncAttributeMaxDynamicSharedMemorySize, SMEM_TOTAL);
    dim3 grid(2, (N + NT - 1) / NT);   // m-pair adjacent in bid -> F L2 reuse
    sct_mma_kernel<<<grid, 256, SMEM_TOTAL>>>(features, (float*)d_out, N);
}